// round 15
// baseline (speedup 1.0000x reference)
#include <cuda_runtime.h>
#include <cuda_bf16.h>

#define TPB     256
#define SSPLIT  25     // fused path split  (V = 128000 = 25*256*4*5)
#define KF      5      // float4 per thread per block chunk
#define GSPLIT  8      // fallback split
#define MAX_B   1024
#define MAX_NT  2048
#define F_NT    512    // fused-path max tokens
#define F_B     256    // fused-path max requests
#define BATCH   8

// cross-block scratch (allocation-free). Zero at load; self-reset per replay.
__device__ unsigned long long g_key[MAX_B];
__device__ int                g_cnt[MAX_B];
__device__ int                g_list[MAX_B];
__device__ int                g_nrej;
__device__ int                g_flag;
__device__ int                g_done;

// ---- shared epilogue: block reduce + packed-key atomic combine -------------
__device__ __forceinline__ void combine_and_write(
    float best, int bidx, int r, int pos, int nact,
    float* __restrict__ out, int L)
{
    const int tid = threadIdx.x;
    #pragma unroll
    for (int off = 16; off > 0; off >>= 1) {
        const float ov = __shfl_down_sync(0xffffffffu, best, off);
        const int   oi = __shfl_down_sync(0xffffffffu, bidx, off);
        if (ov > best || (ov == best && oi < bidx)) { best = ov; bidx = oi; }
    }
    __shared__ float wv[TPB / 32];
    __shared__ int   wi[TPB / 32];
    const int warp = tid >> 5, lane = tid & 31;
    if (lane == 0) { wv[warp] = best; wi[warp] = bidx; }
    __syncthreads();

    if (tid == 0) {
        #pragma unroll
        for (int w = 1; w < TPB / 32; w++) {
            if (wv[w] > best || (wv[w] == best && wi[w] < bidx)) {
                best = wv[w]; bidx = wi[w];
            }
        }
        const unsigned long long key =
            ((unsigned long long)__float_as_uint(best) << 32) |
            (unsigned long long)(~(unsigned)bidx);
        atomicMax(&g_key[r], key);
        __threadfence();
        const int old = atomicAdd(&g_cnt[r], 1);
        if (old == nact - 1) {
            const unsigned long long k = atomicMax(&g_key[r], 0ULL);
            const int idx = (int)(~(unsigned)(k & 0xffffffffULL));
            out[(size_t)r * (L + 1) + pos] = (float)idx;
            g_key[r] = 0ULL;
            g_cnt[r] = 0;
        }
    }
}

// ============ FUSED single-launch kernel (V=128000, L==4, NT<=512) ==========
__global__ void __launch_bounds__(TPB)
fused_kernel(const float* __restrict__ draft_probs,
             const float* __restrict__ target_probs,
             const float* __restrict__ uniform_probs,
             const int*   __restrict__ draft_token_ids,
             const int*   __restrict__ cu,
             const int*   __restrict__ bonus,
             float*       __restrict__ out,
             int B, int NT, int V, int L)
{
    __shared__ int   sid[F_NT];
    __shared__ float stp[F_NT];
    __shared__ float sdp[F_NT];
    __shared__ float su [F_NT];
    __shared__ int   scu[F_B];
    __shared__ int   wcnt[TPB / 32];

    const int bid = blockIdx.x;
    const int tid = threadIdx.x;

    if (bid == 0) {
        // ---- 2-round scan: (cu || ids) -> probs (flat token index) ----
        for (int t = tid; t < NT; t += TPB) sid[t] = __ldg(&draft_token_ids[t]);
        for (int r = tid; r < B; r += TPB)  scu[r] = __ldg(&cu[r]);
        __syncthreads();
        for (int t = tid; t < NT; t += TPB) {
            const int idv = sid[t];
            stp[t] = __ldg(&target_probs[(size_t)t * V + idv]);
            sdp[t] = __ldg(&draft_probs [(size_t)t * V + idv]);
            su [t] = __ldg(&uniform_probs[t]);
        }
        __syncthreads();

        const int r      = tid;
        const bool activ = (r < B);
        int start = 0, end = 0;
        if (activ) { start = (r == 0) ? 0 : scu[r - 1]; end = scu[r]; }
        const int nd  = end - start;
        const int lim = (nd < L) ? nd : L;

        float pi = 1.0f, U = 1.0f;
        int last = -1;
        for (int j = 0; j < lim; j++) {
            const int t = start + j;
            const float dpj = sdp[t];
            const float ratio = (dpj > 0.0f) ? (stp[t] / dpj) : 1.0f;
            pi = fminf(pi * ratio, 1.0f);
            U *= su[t];
            if ((dpj > 0.0f) && (pi >= U)) last = j;
        }

        const int rejected  = (activ && nd > 0 && last != nd - 1) ? 1 : 0;
        const int write_col = rejected ? (last + 1) : nd;

        if (activ) {
            float* orow = out + (size_t)r * (L + 1);
            for (int j = 0; j <= L; j++) {
                float v = -1.0f;
                if (j < L && j <= last) v = (float)sid[start + j];
                orow[j] = v;
            }
            if (!rejected) orow[write_col] = (float)__ldg(&bonus[r]);
        }

        int rec = start + last + 1;
        rec = (rec < 0) ? 0 : rec;
        rec = (rec > NT - 1) ? (NT - 1) : rec;

        // compaction (ballot + cross-warp prefix; deterministic)
        const int warp = tid >> 5, lane = tid & 31;
        const unsigned ball = __ballot_sync(0xffffffffu, rejected);
        const int rank = __popc(ball & ((1u << lane) - 1));
        if (lane == 0) wcnt[warp] = __popc(ball);
        __syncthreads();
        int base = 0, total = 0;
        #pragma unroll
        for (int w = 0; w < TPB / 32; w++) {
            if (w < warp) base += wcnt[w];
            total += wcnt[w];
        }
        if (rejected)
            g_list[base + rank] = r | (write_col << 8) | (rec << 12);
        if (tid == 0) g_nrej = total;

        __threadfence();
        __syncthreads();
        if (tid == 0) atomicExch(&g_flag, 1);
    } else {
        // consumers: sleep-spin until producer publishes
        if (tid == 0) {
            volatile int* f = &g_flag;
            while (*f == 0) __nanosleep(32);
            __threadfence();          // acquire
        }
        __syncthreads();
    }

    // ---------------- spec argmax: KF front-issued unmasked loads -----------
    const int nrej = g_nrej;
    const int row  = bid / SSPLIT;
    const int s    = bid % SSPLIT;

    if (row < nrej) {
        const int e   = g_list[row];
        const int r   = e & 0xff;
        const int pos = (e >> 8) & 0xf;
        const int rec = e >> 12;

        const float4* row4 = reinterpret_cast<const float4*>(
            target_probs + (size_t)rec * V);
        const int n4beg = s * (KF * TPB);

        float m[KF];
        const float4* p = row4 + n4beg + tid;
        #pragma unroll
        for (int k = 0; k < KF; k++) {
            const float4 v = __ldg(p + k * TPB);
            m[k] = fmaxf(fmaxf(v.x, v.y), fmaxf(v.z, v.w));
        }

        float M = m[0];
        #pragma unroll
        for (int k = 1; k < KF; k++) M = fmaxf(M, m[k]);

        int kwin = KF - 1;
        #pragma unroll
        for (int k = KF - 2; k >= 0; k--) if (m[k] == M) kwin = k;
        const int bb4 = n4beg + tid + kwin * TPB;

        const float4 v = __ldg(&row4[bb4]);         // L1-hit reload
        const int bidx = (bb4 << 2) + ((v.x == M) ? 0 : (v.y == M) ? 1
                                     : (v.z == M) ? 2 : 3);

        combine_and_write(M, bidx, r, pos, SSPLIT, out, L);
    }

    // global finisher resets the flag for the next graph replay
    if (tid == 0) {
        __threadfence();
        const int d = atomicAdd(&g_done, 1);
        if (d == (int)gridDim.x - 1) { g_flag = 0; g_done = 0; }
    }
}

// ===================== FALLBACK: proven two-kernel path =====================
__global__ void __launch_bounds__(512)
scan_compact(const float* __restrict__ draft_probs,
             const float* __restrict__ target_probs,
             const float* __restrict__ uniform_probs,
             const int*   __restrict__ draft_token_ids,
             const int*   __restrict__ cu,
             const int*   __restrict__ bonus,
             float*       __restrict__ out,
             int B, int NT, int V, int L)
{
    __shared__ int   sid[MAX_NT];
    __shared__ float stp[MAX_NT];
    __shared__ float sdp[MAX_NT];
    __shared__ float su [MAX_NT];
    __shared__ int   scu[MAX_B];
    __shared__ int   wcnt[16];

    const int tid = threadIdx.x;

    for (int r = tid; r < B; r += 512) scu[r] = __ldg(&cu[r]);
    for (int t = tid; t < NT; t += 512) sid[t] = __ldg(&draft_token_ids[t]);
    __syncthreads();
    for (int t = tid; t < NT; t += 512) {
        const int idv = sid[t];
        stp[t] = __ldg(&target_probs[(size_t)t * V + idv]);
        sdp[t] = __ldg(&draft_probs [(size_t)t * V + idv]);
        su [t] = __ldg(&uniform_probs[t]);
    }
    __syncthreads();

    const int r      = tid;
    const bool activ = (r < B);
    int start = 0, end = 0;
    if (activ) { start = (r == 0) ? 0 : scu[r - 1]; end = scu[r]; }
    const int nd  = end - start;
    const int lim = (nd < L) ? nd : L;

    float pi = 1.0f, U = 1.0f;
    int last = -1;
    for (int j = 0; j < lim; j++) {
        const int t = start + j;
        const float dpj = sdp[t];
        const float ratio = (dpj > 0.0f) ? (stp[t] / dpj) : 1.0f;
        pi = fminf(pi * ratio, 1.0f);
        U *= su[t];
        if ((dpj > 0.0f) && (pi >= U)) last = j;
    }

    const int rejected  = (activ && nd > 0 && last != nd - 1) ? 1 : 0;
    const int write_col = rejected ? (last + 1) : nd;

    if (activ) {
        float* orow = out + (size_t)r * (L + 1);
        for (int j = 0; j <= L; j++) {
            float v = -1.0f;
            if (j < L && j <= last) v = (float)sid[start + j];
            orow[j] = v;
        }
        if (!rejected) orow[write_col] = (float)__ldg(&bonus[r]);
    }

    int rec = start + last + 1;
    rec = (rec < 0) ? 0 : rec;
    rec = (rec > NT - 1) ? (NT - 1) : rec;

    const int warp = tid >> 5, lane = tid & 31;
    const unsigned ball = __ballot_sync(0xffffffffu, rejected);
    const int rank = __popc(ball & ((1u << lane) - 1));
    if (lane == 0) wcnt[warp] = __popc(ball);
    __syncthreads();
    int base = 0, total = 0;
    #pragma unroll
    for (int w = 0; w < 16; w++) {
        if (w < warp) base += wcnt[w];
        total += wcnt[w];
    }
    if (rejected)
        g_list[base + rank] = r | (write_col << 8) | (rec << 12);
    if (tid == 0) g_nrej = total;
}

__global__ void __launch_bounds__(TPB)
argmax_generic(const float* __restrict__ target_probs,
               float* __restrict__ out, int V, int L)
{
    const int row = blockIdx.x / GSPLIT;
    if (row >= g_nrej) return;
    const int s   = blockIdx.x % GSPLIT;
    const int tid = threadIdx.x;

    const int e   = g_list[row];
    const int r   = e & 0xff;
    const int pos = (e >> 8) & 0xf;
    const int rec = e >> 12;

    const int chunk = (((V + GSPLIT - 1) / GSPLIT) + 3) & ~3;
    const int nact  = (V + chunk - 1) / chunk;
    if (s >= nact) return;
    const int beg = s * chunk;
    const int fin = min(V, beg + chunk);

    const float*  rowp = target_probs + (size_t)rec * V;
    const float4* row4 = reinterpret_cast<const float4*>(rowp);
    const int n4beg = beg >> 2;
    const int n4end = fin >> 2;

    float  best  = -1.0f;
    int    bbase = -1;
    float4 bv    = make_float4(0.f, 0.f, 0.f, 0.f);

    for (int i0 = n4beg + tid; i0 < n4end; i0 += BATCH * TPB) {
        float4 vv[BATCH];
        #pragma unroll
        for (int k = 0; k < BATCH; k++) {
            const int ik = i0 + k * TPB;
            const int safe = (ik < n4end) ? ik : i0;
            vv[k] = __ldg(&row4[safe]);
        }
        #pragma unroll
        for (int k = 0; k < BATCH; k++) {
            const int ik = i0 + k * TPB;
            const float m = fmaxf(fmaxf(vv[k].x, vv[k].y),
                                  fmaxf(vv[k].z, vv[k].w));
            if ((ik < n4end) && (m > best)) {
                best = m; bbase = ik << 2; bv = vv[k];
            }
        }
    }

    int bidx = 0x7fffffff;
    if (bbase >= 0) {
        bidx = bbase + ((bv.x == best) ? 0 : (bv.y == best) ? 1
                      : (bv.z == best) ? 2 : 3);
    }
    {
        const int t0 = n4end << 2;
        if (tid < fin - t0) {
            const float vv2 = __ldg(&rowp[t0 + tid]);
            const int   ii  = t0 + tid;
            if (vv2 > best || (vv2 == best && ii < bidx)) { best = vv2; bidx = ii; }
        }
    }

    combine_and_write(best, bidx, r, pos, nact, out, L);
}

extern "C" void kernel_launch(void* const* d_in, const int* in_sizes, int n_in,
                              void* d_out, int out_size) {
    const float* draft_probs     = (const float*)d_in[0];
    const float* target_probs    = (const float*)d_in[1];
    const float* uniform_probs   = (const float*)d_in[2];
    const int*   draft_token_ids = (const int*)  d_in[3];
    const int*   cu              = (const int*)  d_in[4];
    const int*   bonus           = (const int*)  d_in[5];
    float*       out             = (float*)d_out;

    const int NT = in_sizes[3];
    const int B  = in_sizes[4];
    const int V  = in_sizes[0] / NT;
    const int L  = out_size / B - 1;

    if (V == SSPLIT * TPB * 4 * KF && L <= 15 && NT <= F_NT && B <= F_B) {
        fused_kernel<<<B * SSPLIT, TPB>>>(draft_probs, target_probs,
                                          uniform_probs, draft_token_ids,
                                          cu, bonus, out, B, NT, V, L);
    } else {
        scan_compact<<<1, 512>>>(draft_probs, target_probs, uniform_probs,
                                 draft_token_ids, cu, bonus, out, B, NT, V, L);
        argmax_generic<<<B * GSPLIT, TPB>>>(target_probs, out, V, L);
    }
}

// round 17
// speedup vs baseline: 1.6493x; 1.6493x over previous
#include <cuda_runtime.h>
#include <cuda_bf16.h>

#define TPB     256
#define SSPLIT  25     // spec path: V = 128000 = 25 * 256 * 4 * 5
#define KF      5
#define PGRID   1184   // persistent grid: 148 SMs x 8 CTAs (28-reg body)
#define GSPLIT  8      // fallback split
#define MAX_B   1024
#define MAX_NT  2048
#define BATCH   8

// cross-kernel scratch (allocation-free). g_key/g_cnt zero at load and
// self-reset by the finisher -> deterministic across graph replays.
__device__ unsigned long long g_key[MAX_B];
__device__ int                g_cnt[MAX_B];
__device__ int                g_list[MAX_B];
__device__ int                g_nrej;

// ---- shared epilogue: block reduce + packed-key atomic combine -------------
__device__ __forceinline__ void combine_and_write(
    float best, int bidx, int r, int pos, int nact,
    float* __restrict__ out, int L)
{
    const int tid = threadIdx.x;
    #pragma unroll
    for (int off = 16; off > 0; off >>= 1) {
        const float ov = __shfl_down_sync(0xffffffffu, best, off);
        const int   oi = __shfl_down_sync(0xffffffffu, bidx, off);
        if (ov > best || (ov == best && oi < bidx)) { best = ov; bidx = oi; }
    }
    __shared__ float wv[TPB / 32];
    __shared__ int   wi[TPB / 32];
    const int warp = tid >> 5, lane = tid & 31;
    if (lane == 0) { wv[warp] = best; wi[warp] = bidx; }
    __syncthreads();

    if (tid == 0) {
        #pragma unroll
        for (int w = 1; w < TPB / 32; w++) {
            if (wv[w] > best || (wv[w] == best && wi[w] < bidx)) {
                best = wv[w]; bidx = wi[w];
            }
        }
        const unsigned long long key =
            ((unsigned long long)__float_as_uint(best) << 32) |
            (unsigned long long)(~(unsigned)bidx);
        atomicMax(&g_key[r], key);
        __threadfence();
        const int old = atomicAdd(&g_cnt[r], 1);
        if (old == nact - 1) {
            const unsigned long long k = atomicMax(&g_key[r], 0ULL);
            const int idx = (int)(~(unsigned)(k & 0xffffffffULL));
            out[(size_t)r * (L + 1) + pos] = (float)idx;
            g_key[r] = 0ULL;
            g_cnt[r] = 0;
        }
    }
    __syncthreads();    // protect wv/wi reuse across persistent-loop iterations
}

// ---------- Kernel A: token-parallel gather + per-request scan --------------
// skip_rej_cell: when 1 (PDL path), A does not write the recovered-token cell
// for rejected rows — kernel B's finisher owns it (disjoint writes).
__global__ void __launch_bounds__(512)
scan_compact(const float* __restrict__ draft_probs,
             const float* __restrict__ target_probs,
             const float* __restrict__ uniform_probs,
             const int*   __restrict__ draft_token_ids,
             const int*   __restrict__ cu,
             const int*   __restrict__ bonus,
             float*       __restrict__ out,
             int B, int NT, int V, int L, int use_pdl)
{
    __shared__ int   sid[MAX_NT];
    __shared__ float stp[MAX_NT];
    __shared__ float sdp[MAX_NT];
    __shared__ float su [MAX_NT];
    __shared__ int   scu[MAX_B];
    __shared__ int   wcnt[16];

    const int tid = threadIdx.x;

    // round 1: cu and token ids (independent, concurrent)
    for (int r = tid; r < B; r += 512) scu[r] = __ldg(&cu[r]);
    for (int t = tid; t < NT; t += 512) sid[t] = __ldg(&draft_token_ids[t]);
    __syncthreads();

    // round 2: prob/uniform gathers, token-parallel (one latency round)
    for (int t = tid; t < NT; t += 512) {
        const int idv = sid[t];
        stp[t] = __ldg(&target_probs[(size_t)t * V + idv]);
        sdp[t] = __ldg(&draft_probs [(size_t)t * V + idv]);
        su [t] = __ldg(&uniform_probs[t]);
    }
    __syncthreads();

    const int r      = tid;
    const bool activ = (r < B);
    int start = 0, end = 0;
    if (activ) { start = (r == 0) ? 0 : scu[r - 1]; end = scu[r]; }
    const int nd  = end - start;
    const int lim = (nd < L) ? nd : L;

    float pi = 1.0f, U = 1.0f;
    int last = -1;
    for (int j = 0; j < lim; j++) {
        const int t = start + j;
        const float dpj = sdp[t];
        const float ratio = (dpj > 0.0f) ? (stp[t] / dpj) : 1.0f;
        pi = fminf(pi * ratio, 1.0f);
        U *= su[t];
        if ((dpj > 0.0f) && (pi >= U)) last = j;
    }

    const int rejected  = (activ && nd > 0 && last != nd - 1) ? 1 : 0;
    const int write_col = rejected ? (last + 1) : nd;

    int rec = start + last + 1;
    rec = (rec < 0) ? 0 : rec;
    rec = (rec > NT - 1) ? (NT - 1) : rec;

    // compaction (ballot + cross-warp prefix; deterministic order)
    const int warp = tid >> 5, lane = tid & 31;
    const unsigned ball = __ballot_sync(0xffffffffu, rejected);
    const int rank = __popc(ball & ((1u << lane) - 1));
    if (lane == 0) wcnt[warp] = __popc(ball);
    __syncthreads();
    int base = 0, total = 0;
    #pragma unroll
    for (int w = 0; w < 16; w++) {
        if (w < warp) base += wcnt[w];
        total += wcnt[w];
    }
    if (rejected)
        g_list[base + rank] = r | (write_col << 8) | (rec << 12);
    if (tid == 0) g_nrej = total;

    // release the dependent grid as early as possible (PDL path)
    __threadfence();
    __syncthreads();
#if __CUDA_ARCH__ >= 900
    if (use_pdl && tid == 0) cudaTriggerProgrammaticLaunchCompletion();
#endif

    // output rows. On the PDL path, skip rejected rows' recovered cell.
    if (activ) {
        float* orow = out + (size_t)r * (L + 1);
        for (int j = 0; j <= L; j++) {
            if (use_pdl && rejected && j == write_col) continue;  // B owns it
            float v = -1.0f;
            if (j < L && j <= last) v = (float)sid[start + j];
            orow[j] = v;
        }
        if (!rejected) orow[write_col] = (float)__ldg(&bonus[r]);
    }
}

// -------- Kernel B (PDL, persistent): spec KF=5 front-issued argmax ---------
__global__ void __launch_bounds__(TPB)
argmax_spec_persistent(const float* __restrict__ target_probs,
                       float* __restrict__ out, int V, int L)
{
#if __CUDA_ARCH__ >= 900
    cudaGridDependencySynchronize();   // wait for scan_compact's trigger
#endif
    const int tid   = threadIdx.x;
    const int total = g_nrej * SSPLIT;

    for (int item = blockIdx.x; item < total; item += gridDim.x) {
        const int row = item / SSPLIT;
        const int s   = item % SSPLIT;

        const int e   = g_list[row];
        const int r   = e & 0xff;
        const int pos = (e >> 8) & 0xf;
        const int rec = e >> 12;

        const float4* row4 = reinterpret_cast<const float4*>(
            target_probs + (size_t)rec * V);
        const int n4beg = s * (KF * TPB);      // chunk = KF*TPB float4, exact

        float m[KF];
        const float4* p = row4 + n4beg + tid;
        // KF front-issued unmasked loads; v dies into max4 immediately
        #pragma unroll
        for (int k = 0; k < KF; k++) {
            const float4 v = __ldg(p + k * TPB);
            m[k] = fmaxf(fmaxf(v.x, v.y), fmaxf(v.z, v.w));
        }

        float M = m[0];
        #pragma unroll
        for (int k = 1; k < KF; k++) M = fmaxf(M, m[k]);

        // smallest k with m[k]==M (global index grows with k)
        int kwin = KF - 1;
        #pragma unroll
        for (int k = KF - 2; k >= 0; k--) if (m[k] == M) kwin = k;
        const int bb4 = n4beg + tid + kwin * TPB;

        // decode winning lane (L1-hit reload), first occurrence within float4
        const float4 v = __ldg(&row4[bb4]);
        const int bidx = (bb4 << 2) + ((v.x == M) ? 0 : (v.y == M) ? 1
                                     : (v.z == M) ? 2 : 3);

        combine_and_write(M, bidx, r, pos, SSPLIT, out, L);
    }
}

// ---------- Kernel B (generic fallback): proven batch-8 masked body ---------
__global__ void __launch_bounds__(TPB)
argmax_generic(const float* __restrict__ target_probs,
               float* __restrict__ out, int V, int L)
{
    const int row = blockIdx.x / GSPLIT;
    if (row >= g_nrej) return;
    const int s   = blockIdx.x % GSPLIT;
    const int tid = threadIdx.x;

    const int e   = g_list[row];
    const int r   = e & 0xff;
    const int pos = (e >> 8) & 0xf;
    const int rec = e >> 12;

    const int chunk = (((V + GSPLIT - 1) / GSPLIT) + 3) & ~3;
    const int nact  = (V + chunk - 1) / chunk;
    if (s >= nact) return;
    const int beg = s * chunk;
    const int fin = min(V, beg + chunk);

    const float*  rowp = target_probs + (size_t)rec * V;
    const float4* row4 = reinterpret_cast<const float4*>(rowp);
    const int n4beg = beg >> 2;
    const int n4end = fin >> 2;

    float  best  = -1.0f;
    int    bbase = -1;
    float4 bv    = make_float4(0.f, 0.f, 0.f, 0.f);

    for (int i0 = n4beg + tid; i0 < n4end; i0 += BATCH * TPB) {
        float4 vv[BATCH];
        #pragma unroll
        for (int k = 0; k < BATCH; k++) {
            const int ik = i0 + k * TPB;
            const int safe = (ik < n4end) ? ik : i0;
            vv[k] = __ldg(&row4[safe]);
        }
        #pragma unroll
        for (int k = 0; k < BATCH; k++) {
            const int ik = i0 + k * TPB;
            const float m = fmaxf(fmaxf(vv[k].x, vv[k].y),
                                  fmaxf(vv[k].z, vv[k].w));
            if ((ik < n4end) && (m > best)) {
                best = m; bbase = ik << 2; bv = vv[k];
            }
        }
    }

    int bidx = 0x7fffffff;
    if (bbase >= 0) {
        bidx = bbase + ((bv.x == best) ? 0 : (bv.y == best) ? 1
                      : (bv.z == best) ? 2 : 3);
    }
    {
        const int t0 = n4end << 2;
        if (tid < fin - t0) {
            const float vv2 = __ldg(&rowp[t0 + tid]);
            const int   ii  = t0 + tid;
            if (vv2 > best || (vv2 == best && ii < bidx)) { best = vv2; bidx = ii; }
        }
    }

    combine_and_write(best, bidx, r, pos, nact, out, L);
}

extern "C" void kernel_launch(void* const* d_in, const int* in_sizes, int n_in,
                              void* d_out, int out_size) {
    const float* draft_probs     = (const float*)d_in[0];
    const float* target_probs    = (const float*)d_in[1];
    const float* uniform_probs   = (const float*)d_in[2];
    const int*   draft_token_ids = (const int*)  d_in[3];
    const int*   cu              = (const int*)  d_in[4];
    const int*   bonus           = (const int*)  d_in[5];
    float*       out             = (float*)d_out;

    const int NT = in_sizes[3];
    const int B  = in_sizes[4];
    const int V  = in_sizes[0] / NT;
    const int L  = out_size / B - 1;

    const bool spec = (V == SSPLIT * TPB * 4 * KF) && (L <= 15) && (B <= 256);

    scan_compact<<<1, 512>>>(draft_probs, target_probs, uniform_probs,
                             draft_token_ids, cu, bonus, out,
                             B, NT, V, L, spec ? 1 : 0);

    if (spec) {
        // persistent one-wave grid + programmatic dependent launch
        cudaLaunchConfig_t cfg = {};
        cfg.gridDim  = dim3(PGRID, 1, 1);
        cfg.blockDim = dim3(TPB, 1, 1);
        cfg.dynamicSmemBytes = 0;
        cfg.stream = 0;
        cudaLaunchAttribute attrs[1];
        attrs[0].id = cudaLaunchAttributeProgrammaticStreamSerialization;
        attrs[0].val.programmaticStreamSerializationAllowed = 1;
        cfg.attrs = attrs;
        cfg.numAttrs = 1;
        cudaLaunchKernelEx(&cfg, argmax_spec_persistent, target_probs, out, V, L);
    } else {
        argmax_generic<<<B * GSPLIT, TPB>>>(target_probs, out, V, L);
    }
}